// round 15
// baseline (speedup 1.0000x reference)
#include <cuda_runtime.h>
#include <cuda_fp16.h>
#include <cstdint>

// ===========================================================================
// WindowAttention fused, HMMA (mma.sync m16n8k16 f16 -> f32)
//   1 window per CTA, 256 threads / 8 warps, 2 CTAs per SM.
//   Phase 2: register-resident softmax, 2 heads in flight, zero barriers.
// ===========================================================================

#define DIMC    192
#define SCALE_F 0.17677669529663687f

// ---- smem byte offsets ----------------------------------------------------
// fp16 row stride 400B (==16 mod 128 -> ldmatrix conflict-free); vt 144B
#define QS_OFF   0          // X staging, then Q / O : 64 x 200 halfs = 25600 B
#define KS_OFF   25600      // K : 25600 B
#define VT_OFF   51200      // V^T : 192 x 72 halfs = 27648 B
#define WBU_OFF  78848      // 2 x 12800 weight double-buffer
#define WB_SZ    12800
#define BIAS_OFF 104448     // bias_table fp16: 2700 B
#define REL_OFF  107152     // rel_idx u8: 4096 B
#define SM_TOTAL 111248

// prepped fp16 weights (row-major [out_ch][k])
__device__ __half g_wq[576 * 192];
__device__ __half g_wp[192 * 192];

// ---------------------------------------------------------------------------
__device__ __forceinline__ uint32_t s2u(const void* p) {
    uint32_t a;
    asm("{ .reg .u64 t; cvta.to.shared.u64 t, %1; cvt.u32.u64 %0, t; }"
        : "=r"(a) : "l"(p));
    return a;
}

__device__ __forceinline__ void ldsm4(uint32_t r[4], uint32_t a) {
    asm volatile("ldmatrix.sync.aligned.m8n8.x4.shared.b16 {%0,%1,%2,%3}, [%4];"
        : "=r"(r[0]), "=r"(r[1]), "=r"(r[2]), "=r"(r[3]) : "r"(a));
}

__device__ __forceinline__ void hmma(float c[4], const uint32_t a[4],
                                     uint32_t b0, uint32_t b1) {
    asm volatile(
        "mma.sync.aligned.m16n8k16.row.col.f32.f16.f16.f32 "
        "{%0,%1,%2,%3}, {%4,%5,%6,%7}, {%8,%9}, {%0,%1,%2,%3};"
        : "+f"(c[0]), "+f"(c[1]), "+f"(c[2]), "+f"(c[3])
        : "r"(a[0]), "r"(a[1]), "r"(a[2]), "r"(a[3]), "r"(b0), "r"(b1));
}

__device__ __forceinline__ uint32_t h2u(__half2 h) {
    union { __half2 h; uint32_t u; } c;
    c.h = h;
    return c.u;
}

#define CP16(dst, src) asm volatile("cp.async.cg.shared.global [%0], [%1], 16;" :: "r"(dst), "l"(src))
#define CPCOMMIT()     asm volatile("cp.async.commit_group;" ::: "memory")
#define CPWAIT0()      asm volatile("cp.async.wait_group 0;" ::: "memory")

// stage one 32x192 fp16 weight chunk (row stride 400B in smem)
__device__ __forceinline__ void prefetch32(uint32_t wbAddr, const __half* src,
                                           int tid) {
    #pragma unroll
    for (int i = 0; i < 3; i++) {
        int idx = tid + 256 * i;          // 0..767 = 32 rows * 24 segs
        int row = idx / 24, seg = idx % 24;
        CP16(wbAddr + row * 400 + seg * 16,
             (const char*)src + row * 384 + seg * 16);
    }
}

// ---------------------------------------------------------------------------
__global__ void wa_prep(const float* __restrict__ qkv_w,
                        const float* __restrict__ proj_w)
{
    int i = blockIdx.x * blockDim.x + threadIdx.x;
    if (i < 576 * 192) g_wq[i] = __float2half_rn(qkv_w[i]);
    if (i < 192 * 192) g_wp[i] = __float2half_rn(proj_w[i]);
}

// ---------------------------------------------------------------------------
__global__ void __launch_bounds__(256, 2)
wa_main(const float* __restrict__ x,
        const float* __restrict__ qkv_b,
        const float* __restrict__ proj_b,
        const float* __restrict__ bias_table,
        const int*   __restrict__ rel_idx,
        float*       __restrict__ out)
{
    extern __shared__ __align__(16) char sm[];
    const uint32_t smb = s2u(sm);
    const int tid  = threadIdx.x;
    const int wid  = tid >> 5;
    const int lane = tid & 31;
    const int m0   = (wid & 3) * 16;     // warp m-tile base
    const int ng   = wid >> 2;           // warp n-group / head parity (0/1)
    const int m_r  = m0 + (lane >> 2);
    const int n_c  = 2 * (lane & 3);     // col-pair within n8 block

    // A-fragment ldmatrix address (m16 tile, 16B k-split), reused ph1/ph3
    const uint32_t aRowQ = smb + QS_OFF + (m0 + (lane & 15)) * 400
                         + ((lane >> 4) << 4);
    // B-row base pattern for n16 ldmatrix.x4 (phase 1/3 weights)
    const uint32_t bSel  = (ng * 16 + ((lane >> 4) << 3) + (lane & 7)) * 400
                         + (((lane >> 3) & 1) << 4);

    prefetch32(smb + WBU_OFF, g_wq, tid);   // qkv chunk 0
    CPCOMMIT();

    // stage x -> fp16 in QS region (stride 400B)
    {
        const float4* xg = (const float4*)(x + (size_t)blockIdx.x * 64 * DIMC);
        #pragma unroll
        for (int i = 0; i < 12; i++) {
            int idx = tid + 256 * i;           // 3072 float4 = 64 rows * 48
            int r = idx / 48, c4 = idx % 48;
            float4 v = xg[idx];
            __half2* d = (__half2*)(sm + QS_OFF + r * 400 + c4 * 8);
            d[0] = __floats2half2_rn(v.x, v.y);
            d[1] = __floats2half2_rn(v.z, v.w);
        }
    }
    for (int i = tid; i < 1350; i += 256)
        ((__half*)(sm + BIAS_OFF))[i] = __float2half_rn(bias_table[i]);
    for (int i = tid; i < 4096; i += 256)
        ((uint8_t*)(sm + REL_OFF))[i] = (uint8_t)rel_idx[i];
    __syncthreads();

    // cache X A-fragments in registers (k = 0..191 in 12 steps)
    uint32_t af[12][4];
    #pragma unroll
    for (int k = 0; k < 12; k++) ldsm4(af[k], aRowQ + k * 32);

    CPWAIT0();
    __syncthreads();     // chunk0 visible; all X reads complete

    // ================= phase 1: qkv GEMM, 18 chunks of 32 channels =========
    for (int cc = 0; cc < 18; cc++) {
        if (cc < 17) {
            prefetch32(smb + WBU_OFF + ((cc + 1) & 1) * WB_SZ,
                       g_wq + (cc + 1) * 32 * 192, tid);
            CPCOMMIT();
        }
        float acc[2][4] = {};
        uint32_t bRow = smb + WBU_OFF + (cc & 1) * WB_SZ + bSel;
        #pragma unroll
        for (int k = 0; k < 12; k++) {
            uint32_t b[4]; ldsm4(b, bRow + k * 32);
            hmma(acc[0], af[k], b[0], b[1]);
            hmma(acc[1], af[k], b[2], b[3]);
        }
        if (cc < 6) {                          // Q (pre-scaled)
            #pragma unroll
            for (int jj = 0; jj < 2; jj++) {
                int col = cc * 32 + ng * 16 + n_c + 8 * jj;
                float b0 = __ldg(qkv_b + col), b1 = __ldg(qkv_b + col + 1);
                *(__half2*)(sm + QS_OFF + m_r * 400 + col * 2) =
                    __floats2half2_rn((acc[jj][0] + b0) * SCALE_F,
                                      (acc[jj][1] + b1) * SCALE_F);
                *(__half2*)(sm + QS_OFF + (m_r + 8) * 400 + col * 2) =
                    __floats2half2_rn((acc[jj][2] + b0) * SCALE_F,
                                      (acc[jj][3] + b1) * SCALE_F);
            }
        } else if (cc < 12) {                  // K
            #pragma unroll
            for (int jj = 0; jj < 2; jj++) {
                int col = (cc - 6) * 32 + ng * 16 + n_c + 8 * jj;
                float b0 = __ldg(qkv_b + 192 + col), b1 = __ldg(qkv_b + 192 + col + 1);
                *(__half2*)(sm + KS_OFF + m_r * 400 + col * 2) =
                    __floats2half2_rn(acc[jj][0] + b0, acc[jj][1] + b1);
                *(__half2*)(sm + KS_OFF + (m_r + 8) * 400 + col * 2) =
                    __floats2half2_rn(acc[jj][2] + b0, acc[jj][3] + b1);
            }
        } else {                               // V -> vt[d][tok]
            __half* vt = (__half*)(sm + VT_OFF);
            #pragma unroll
            for (int jj = 0; jj < 2; jj++) {
                int d = (cc - 12) * 32 + ng * 16 + n_c + 8 * jj;
                float b0 = __ldg(qkv_b + 384 + d), b1 = __ldg(qkv_b + 384 + d + 1);
                vt[d * 72 + m_r]           = __float2half_rn(acc[jj][0] + b0);
                vt[(d + 1) * 72 + m_r]     = __float2half_rn(acc[jj][1] + b1);
                vt[d * 72 + m_r + 8]       = __float2half_rn(acc[jj][2] + b0);
                vt[(d + 1) * 72 + m_r + 8] = __float2half_rn(acc[jj][3] + b1);
            }
        }
        if (cc < 17) { CPWAIT0(); __syncthreads(); }
    }

    // prefetch proj chunk 0 now — WBU unused during phase 2
    prefetch32(smb + WBU_OFF, g_wp, tid);
    CPCOMMIT();
    __syncthreads();     // Q/K/V complete

    // ================= phase 2: attention, 2 heads per iter, no barriers ===
    {
        const uint8_t* rl1 = (const uint8_t*)(sm + REL_OFF) + m_r * 64;
        const uint8_t* rl2 = rl1 + 8 * 64;
        const __half*  bt  = (const __half*)(sm + BIAS_OFF);

        #pragma unroll
        for (int it = 0; it < 3; it++) {
            const int h = 2 * it + ng;

            // ---- S = Q_h K_h^T : warp computes m16 x n64 ----
            float sc[8][4] = {};
            {
                uint32_t aR = smb + QS_OFF + (m0 + (lane & 15)) * 400 + h * 64
                            + ((lane >> 4) << 4);
                uint32_t bR = smb + KS_OFF
                            + (((lane >> 4) << 3) + (lane & 7)) * 400
                            + h * 64 + (((lane >> 3) & 1) << 4);
                #pragma unroll
                for (int k = 0; k < 2; k++) {
                    uint32_t a[4]; ldsm4(a, aR + k * 32);
                    #pragma unroll
                    for (int g = 0; g < 4; g++) {
                        uint32_t b[4];
                        ldsm4(b, bR + g * 16 * 400 + k * 32);
                        hmma(sc[2 * g],     a, b[0], b[1]);
                        hmma(sc[2 * g + 1], a, b[2], b[3]);
                    }
                }
            }

            // ---- bias add + in-register softmax (rows r1=m_r, r2=m_r+8) ----
            float mx1 = -1e30f, mx2 = -1e30f;
            #pragma unroll
            for (int j = 0; j < 8; j++) {
                int n = 8 * j + n_c;
                sc[j][0] += __half2float(bt[rl1[n]     * 6 + h]);
                sc[j][1] += __half2float(bt[rl1[n + 1] * 6 + h]);
                sc[j][2] += __half2float(bt[rl2[n]     * 6 + h]);
                sc[j][3] += __half2float(bt[rl2[n + 1] * 6 + h]);
                mx1 = fmaxf(mx1, fmaxf(sc[j][0], sc[j][1]));
                mx2 = fmaxf(mx2, fmaxf(sc[j][2], sc[j][3]));
            }
            #pragma unroll
            for (int o = 1; o <= 2; o <<= 1) {
                mx1 = fmaxf(mx1, __shfl_xor_sync(0xffffffffu, mx1, o));
                mx2 = fmaxf(mx2, __shfl_xor_sync(0xffffffffu, mx2, o));
            }
            float s1 = 0.0f, s2 = 0.0f;
            #pragma unroll
            for (int j = 0; j < 8; j++) {
                sc[j][0] = __expf(sc[j][0] - mx1);
                sc[j][1] = __expf(sc[j][1] - mx1);
                sc[j][2] = __expf(sc[j][2] - mx2);
                sc[j][3] = __expf(sc[j][3] - mx2);
                s1 += sc[j][0] + sc[j][1];
                s2 += sc[j][2] + sc[j][3];
            }
            #pragma unroll
            for (int o = 1; o <= 2; o <<= 1) {
                s1 += __shfl_xor_sync(0xffffffffu, s1, o);
                s2 += __shfl_xor_sync(0xffffffffu, s2, o);
            }
            float inv1 = 1.0f / s1, inv2 = 1.0f / s2;

            // pack probs straight into PV A-fragments (fragment layouts match)
            uint32_t pa[4][4];
            #pragma unroll
            for (int kt = 0; kt < 4; kt++) {
                pa[kt][0] = h2u(__floats2half2_rn(sc[2*kt][0]   * inv1, sc[2*kt][1]   * inv1));
                pa[kt][1] = h2u(__floats2half2_rn(sc[2*kt][2]   * inv2, sc[2*kt][3]   * inv2));
                pa[kt][2] = h2u(__floats2half2_rn(sc[2*kt+1][0] * inv1, sc[2*kt+1][1] * inv1));
                pa[kt][3] = h2u(__floats2half2_rn(sc[2*kt+1][2] * inv2, sc[2*kt+1][3] * inv2));
            }

            // ---- O_h = P V_h : warp computes m16 x n32 ----
            float oc[4][4] = {};
            {
                uint32_t bR = smb + VT_OFF
                            + (h * 32 + ((lane >> 4) << 3) + (lane & 7)) * 144
                            + (((lane >> 3) & 1) << 4);
                #pragma unroll
                for (int kt = 0; kt < 4; kt++) {
                    #pragma unroll
                    for (int g = 0; g < 2; g++) {
                        uint32_t b[4];
                        ldsm4(b, bR + g * 16 * 144 + kt * 32);
                        hmma(oc[2 * g],     pa[kt], b[0], b[1]);
                        hmma(oc[2 * g + 1], pa[kt], b[2], b[3]);
                    }
                }
            }
            // overwrite Q slice h with O (own rows, own head cols only)
            #pragma unroll
            for (int j = 0; j < 4; j++) {
                int col = h * 32 + 8 * j + n_c;
                *(__half2*)(sm + QS_OFF + m_r * 400 + col * 2) =
                    __floats2half2_rn(oc[j][0], oc[j][1]);
                *(__half2*)(sm + QS_OFF + (m_r + 8) * 400 + col * 2) =
                    __floats2half2_rn(oc[j][2], oc[j][3]);
            }
        }
    }
    __syncthreads();     // all O written

    // ================= phase 3: proj GEMM, 6 chunks of 32 ==================
    #pragma unroll
    for (int k = 0; k < 12; k++) ldsm4(af[k], aRowQ + k * 32);   // O frags
    CPWAIT0();           // proj chunk 0 (prefetched before phase 2)
    __syncthreads();

    const size_t gbase = (size_t)blockIdx.x * 64;
    for (int g = 0; g < 6; g++) {
        if (g < 5) {
            prefetch32(smb + WBU_OFF + ((g + 1) & 1) * WB_SZ,
                       g_wp + (g + 1) * 32 * 192, tid);
            CPCOMMIT();
        }
        float acc[2][4] = {};
        uint32_t bRow = smb + WBU_OFF + (g & 1) * WB_SZ + bSel;
        #pragma unroll
        for (int k = 0; k < 12; k++) {
            uint32_t b[4]; ldsm4(b, bRow + k * 32);
            hmma(acc[0], af[k], b[0], b[1]);
            hmma(acc[1], af[k], b[2], b[3]);
        }
        #pragma unroll
        for (int jj = 0; jj < 2; jj++) {
            int col = g * 32 + ng * 16 + n_c + 8 * jj;
            float b0 = __ldg(proj_b + col), b1 = __ldg(proj_b + col + 1);
            *(float2*)(out + (gbase + m_r) * 192 + col) =
                make_float2(acc[jj][0] + b0, acc[jj][1] + b1);
            *(float2*)(out + (gbase + m_r + 8) * 192 + col) =
                make_float2(acc[jj][2] + b0, acc[jj][3] + b1);
        }
        if (g < 5) { CPWAIT0(); __syncthreads(); }
    }
}

// ---------------------------------------------------------------------------
extern "C" void kernel_launch(void* const* d_in, const int* in_sizes, int n_in,
                              void* d_out, int out_size)
{
    const float* x          = (const float*)d_in[0];
    const float* qkv_w      = (const float*)d_in[1];
    const float* qkv_b      = (const float*)d_in[2];
    const float* proj_w     = (const float*)d_in[3];
    const float* proj_b     = (const float*)d_in[4];
    const float* bias_table = (const float*)d_in[5];
    const int*   rel_idx    = (const int*)d_in[6];
    float* out = (float*)d_out;
    (void)n_in; (void)out_size;

    int B = in_sizes[0] / (64 * DIMC);    // 4096 windows

    cudaFuncSetAttribute(wa_main, cudaFuncAttributeMaxDynamicSharedMemorySize,
                         SM_TOTAL);

    wa_prep<<<432, 256>>>(qkv_w, proj_w);
    wa_main<<<B, 256, SM_TOTAL>>>(x, qkv_b, proj_b, bias_table, rel_idx, out);
}

// round 16
// speedup vs baseline: 1.0074x; 1.0074x over previous
#include <cuda_runtime.h>
#include <cuda_fp16.h>
#include <cstdint>

// ===========================================================================
// WindowAttention fused, HMMA (mma.sync m16n8k16 f16 -> f32)
//   1 window per CTA, 256 threads / 8 warps, 2 CTAs per SM.
//   Phase 2: register-resident softmax, 2 heads in flight, zero barriers.
// ===========================================================================

#define DIMC    192
#define SCALE_F 0.17677669529663687f

// ---- smem byte offsets ----------------------------------------------------
// fp16 row stride 400B (==16 mod 128 -> ldmatrix conflict-free); vt 144B
#define QS_OFF   0          // X staging, then Q / O : 64 x 200 halfs = 25600 B
#define KS_OFF   25600      // K : 25600 B
#define VT_OFF   51200      // V^T : 192 x 72 halfs = 27648 B
#define WBU_OFF  78848      // 2 x 12800 weight double-buffer
#define WB_SZ    12800
#define BIAS_OFF 104448     // bias_table fp16: 2700 B
#define REL_OFF  107152     // rel_idx u8: 4096 B
#define SM_TOTAL 111248

// prepped fp16 weights (row-major [out_ch][k])
__device__ __half g_wq[576 * 192];
__device__ __half g_wp[192 * 192];

// ---------------------------------------------------------------------------
__device__ __forceinline__ uint32_t s2u(const void* p) {
    uint32_t a;
    asm("{ .reg .u64 t; cvta.to.shared.u64 t, %1; cvt.u32.u64 %0, t; }"
        : "=r"(a) : "l"(p));
    return a;
}

__device__ __forceinline__ void ldsm4(uint32_t r[4], uint32_t a) {
    asm volatile("ldmatrix.sync.aligned.m8n8.x4.shared.b16 {%0,%1,%2,%3}, [%4];"
        : "=r"(r[0]), "=r"(r[1]), "=r"(r[2]), "=r"(r[3]) : "r"(a));
}

__device__ __forceinline__ void hmma(float c[4], const uint32_t a[4],
                                     uint32_t b0, uint32_t b1) {
    asm volatile(
        "mma.sync.aligned.m16n8k16.row.col.f32.f16.f16.f32 "
        "{%0,%1,%2,%3}, {%4,%5,%6,%7}, {%8,%9}, {%0,%1,%2,%3};"
        : "+f"(c[0]), "+f"(c[1]), "+f"(c[2]), "+f"(c[3])
        : "r"(a[0]), "r"(a[1]), "r"(a[2]), "r"(a[3]), "r"(b0), "r"(b1));
}

__device__ __forceinline__ uint32_t h2u(__half2 h) {
    union { __half2 h; uint32_t u; } c;
    c.h = h;
    return c.u;
}

#define CP16(dst, src) asm volatile("cp.async.cg.shared.global [%0], [%1], 16;" :: "r"(dst), "l"(src))
#define CPCOMMIT()     asm volatile("cp.async.commit_group;" ::: "memory")
#define CPWAIT0()      asm volatile("cp.async.wait_group 0;" ::: "memory")

// stage one 32x192 fp16 weight chunk (row stride 400B in smem)
__device__ __forceinline__ void prefetch32(uint32_t wbAddr, const __half* src,
                                           int tid) {
    #pragma unroll
    for (int i = 0; i < 3; i++) {
        int idx = tid + 256 * i;          // 0..767 = 32 rows * 24 segs
        int row = idx / 24, seg = idx % 24;
        CP16(wbAddr + row * 400 + seg * 16,
             (const char*)src + row * 384 + seg * 16);
    }
}

// ---------------------------------------------------------------------------
__global__ void wa_prep(const float* __restrict__ qkv_w,
                        const float* __restrict__ proj_w)
{
    int i = blockIdx.x * blockDim.x + threadIdx.x;
    if (i < 576 * 192) g_wq[i] = __float2half_rn(qkv_w[i]);
    if (i < 192 * 192) g_wp[i] = __float2half_rn(proj_w[i]);
}

// ---------------------------------------------------------------------------
__global__ void __launch_bounds__(256, 2)
wa_main(const float* __restrict__ x,
        const float* __restrict__ qkv_b,
        const float* __restrict__ proj_b,
        const float* __restrict__ bias_table,
        const int*   __restrict__ rel_idx,
        float*       __restrict__ out)
{
    extern __shared__ __align__(16) char sm[];
    const uint32_t smb = s2u(sm);
    const int tid  = threadIdx.x;
    const int wid  = tid >> 5;
    const int lane = tid & 31;
    const int m0   = (wid & 3) * 16;     // warp m-tile base
    const int ng   = wid >> 2;           // warp n-group / head parity (0/1)
    const int m_r  = m0 + (lane >> 2);
    const int n_c  = 2 * (lane & 3);     // col-pair within n8 block

    // A-fragment ldmatrix address (m16 tile, 16B k-split), reused ph1/ph3
    const uint32_t aRowQ = smb + QS_OFF + (m0 + (lane & 15)) * 400
                         + ((lane >> 4) << 4);
    // B-row base pattern for n16 ldmatrix.x4 (phase 1/3 weights)
    const uint32_t bSel  = (ng * 16 + ((lane >> 4) << 3) + (lane & 7)) * 400
                         + (((lane >> 3) & 1) << 4);

    prefetch32(smb + WBU_OFF, g_wq, tid);   // qkv chunk 0
    CPCOMMIT();

    // stage x -> fp16 in QS region (stride 400B)
    {
        const float4* xg = (const float4*)(x + (size_t)blockIdx.x * 64 * DIMC);
        #pragma unroll
        for (int i = 0; i < 12; i++) {
            int idx = tid + 256 * i;           // 3072 float4 = 64 rows * 48
            int r = idx / 48, c4 = idx % 48;
            float4 v = xg[idx];
            __half2* d = (__half2*)(sm + QS_OFF + r * 400 + c4 * 8);
            d[0] = __floats2half2_rn(v.x, v.y);
            d[1] = __floats2half2_rn(v.z, v.w);
        }
    }
    for (int i = tid; i < 1350; i += 256)
        ((__half*)(sm + BIAS_OFF))[i] = __float2half_rn(bias_table[i]);
    for (int i = tid; i < 4096; i += 256)
        ((uint8_t*)(sm + REL_OFF))[i] = (uint8_t)rel_idx[i];
    __syncthreads();

    // cache X A-fragments in registers (k = 0..191 in 12 steps)
    uint32_t af[12][4];
    #pragma unroll
    for (int k = 0; k < 12; k++) ldsm4(af[k], aRowQ + k * 32);

    CPWAIT0();
    __syncthreads();     // chunk0 visible; all X reads complete

    // ================= phase 1: qkv GEMM, 18 chunks of 32 channels =========
    for (int cc = 0; cc < 18; cc++) {
        if (cc < 17) {
            prefetch32(smb + WBU_OFF + ((cc + 1) & 1) * WB_SZ,
                       g_wq + (cc + 1) * 32 * 192, tid);
            CPCOMMIT();
        }
        float acc[2][4] = {};
        uint32_t bRow = smb + WBU_OFF + (cc & 1) * WB_SZ + bSel;
        #pragma unroll
        for (int k = 0; k < 12; k++) {
            uint32_t b[4]; ldsm4(b, bRow + k * 32);
            hmma(acc[0], af[k], b[0], b[1]);
            hmma(acc[1], af[k], b[2], b[3]);
        }
        if (cc < 6) {                          // Q (pre-scaled)
            #pragma unroll
            for (int jj = 0; jj < 2; jj++) {
                int col = cc * 32 + ng * 16 + n_c + 8 * jj;
                float b0 = __ldg(qkv_b + col), b1 = __ldg(qkv_b + col + 1);
                *(__half2*)(sm + QS_OFF + m_r * 400 + col * 2) =
                    __floats2half2_rn((acc[jj][0] + b0) * SCALE_F,
                                      (acc[jj][1] + b1) * SCALE_F);
                *(__half2*)(sm + QS_OFF + (m_r + 8) * 400 + col * 2) =
                    __floats2half2_rn((acc[jj][2] + b0) * SCALE_F,
                                      (acc[jj][3] + b1) * SCALE_F);
            }
        } else if (cc < 12) {                  // K
            #pragma unroll
            for (int jj = 0; jj < 2; jj++) {
                int col = (cc - 6) * 32 + ng * 16 + n_c + 8 * jj;
                float b0 = __ldg(qkv_b + 192 + col), b1 = __ldg(qkv_b + 192 + col + 1);
                *(__half2*)(sm + KS_OFF + m_r * 400 + col * 2) =
                    __floats2half2_rn(acc[jj][0] + b0, acc[jj][1] + b1);
                *(__half2*)(sm + KS_OFF + (m_r + 8) * 400 + col * 2) =
                    __floats2half2_rn(acc[jj][2] + b0, acc[jj][3] + b1);
            }
        } else {                               // V -> vt[d][tok]
            __half* vt = (__half*)(sm + VT_OFF);
            #pragma unroll
            for (int jj = 0; jj < 2; jj++) {
                int d = (cc - 12) * 32 + ng * 16 + n_c + 8 * jj;
                float b0 = __ldg(qkv_b + 384 + d), b1 = __ldg(qkv_b + 384 + d + 1);
                vt[d * 72 + m_r]           = __float2half_rn(acc[jj][0] + b0);
                vt[(d + 1) * 72 + m_r]     = __float2half_rn(acc[jj][1] + b1);
                vt[d * 72 + m_r + 8]       = __float2half_rn(acc[jj][2] + b0);
                vt[(d + 1) * 72 + m_r + 8] = __float2half_rn(acc[jj][3] + b1);
            }
        }
        if (cc < 17) { CPWAIT0(); __syncthreads(); }
    }

    // prefetch proj chunk 0 now — WBU unused during phase 2
    prefetch32(smb + WBU_OFF, g_wp, tid);
    CPCOMMIT();
    __syncthreads();     // Q/K/V complete

    // ================= phase 2: attention, 2 heads per iter, no barriers ===
    {
        const uint8_t* rl1 = (const uint8_t*)(sm + REL_OFF) + m_r * 64;
        const uint8_t* rl2 = rl1 + 8 * 64;
        const __half*  bt  = (const __half*)(sm + BIAS_OFF);

        #pragma unroll
        for (int it = 0; it < 3; it++) {
            const int h = 2 * it + ng;

            // ---- S = Q_h K_h^T : warp computes m16 x n64 ----
            float sc[8][4] = {};
            {
                uint32_t aR = smb + QS_OFF + (m0 + (lane & 15)) * 400 + h * 64
                            + ((lane >> 4) << 4);
                uint32_t bR = smb + KS_OFF
                            + (((lane >> 4) << 3) + (lane & 7)) * 400
                            + h * 64 + (((lane >> 3) & 1) << 4);
                #pragma unroll
                for (int k = 0; k < 2; k++) {
                    uint32_t a[4]; ldsm4(a, aR + k * 32);
                    #pragma unroll
                    for (int g = 0; g < 4; g++) {
                        uint32_t b[4];
                        ldsm4(b, bR + g * 16 * 400 + k * 32);
                        hmma(sc[2 * g],     a, b[0], b[1]);
                        hmma(sc[2 * g + 1], a, b[2], b[3]);
                    }
                }
            }

            // ---- bias add + in-register softmax (rows r1=m_r, r2=m_r+8) ----
            float mx1 = -1e30f, mx2 = -1e30f;
            #pragma unroll
            for (int j = 0; j < 8; j++) {
                int n = 8 * j + n_c;
                sc[j][0] += __half2float(bt[rl1[n]     * 6 + h]);
                sc[j][1] += __half2float(bt[rl1[n + 1] * 6 + h]);
                sc[j][2] += __half2float(bt[rl2[n]     * 6 + h]);
                sc[j][3] += __half2float(bt[rl2[n + 1] * 6 + h]);
                mx1 = fmaxf(mx1, fmaxf(sc[j][0], sc[j][1]));
                mx2 = fmaxf(mx2, fmaxf(sc[j][2], sc[j][3]));
            }
            #pragma unroll
            for (int o = 1; o <= 2; o <<= 1) {
                mx1 = fmaxf(mx1, __shfl_xor_sync(0xffffffffu, mx1, o));
                mx2 = fmaxf(mx2, __shfl_xor_sync(0xffffffffu, mx2, o));
            }
            float s1 = 0.0f, s2 = 0.0f;
            #pragma unroll
            for (int j = 0; j < 8; j++) {
                sc[j][0] = __expf(sc[j][0] - mx1);
                sc[j][1] = __expf(sc[j][1] - mx1);
                sc[j][2] = __expf(sc[j][2] - mx2);
                sc[j][3] = __expf(sc[j][3] - mx2);
                s1 += sc[j][0] + sc[j][1];
                s2 += sc[j][2] + sc[j][3];
            }
            #pragma unroll
            for (int o = 1; o <= 2; o <<= 1) {
                s1 += __shfl_xor_sync(0xffffffffu, s1, o);
                s2 += __shfl_xor_sync(0xffffffffu, s2, o);
            }
            float inv1 = 1.0f / s1, inv2 = 1.0f / s2;

            // pack probs straight into PV A-fragments (fragment layouts match)
            uint32_t pa[4][4];
            #pragma unroll
            for (int kt = 0; kt < 4; kt++) {
                pa[kt][0] = h2u(__floats2half2_rn(sc[2*kt][0]   * inv1, sc[2*kt][1]   * inv1));
                pa[kt][1] = h2u(__floats2half2_rn(sc[2*kt][2]   * inv2, sc[2*kt][3]   * inv2));
                pa[kt][2] = h2u(__floats2half2_rn(sc[2*kt+1][0] * inv1, sc[2*kt+1][1] * inv1));
                pa[kt][3] = h2u(__floats2half2_rn(sc[2*kt+1][2] * inv2, sc[2*kt+1][3] * inv2));
            }

            // ---- O_h = P V_h : warp computes m16 x n32 ----
            float oc[4][4] = {};
            {
                uint32_t bR = smb + VT_OFF
                            + (h * 32 + ((lane >> 4) << 3) + (lane & 7)) * 144
                            + (((lane >> 3) & 1) << 4);
                #pragma unroll
                for (int kt = 0; kt < 4; kt++) {
                    #pragma unroll
                    for (int g = 0; g < 2; g++) {
                        uint32_t b[4];
                        ldsm4(b, bR + g * 16 * 144 + kt * 32);
                        hmma(oc[2 * g],     pa[kt], b[0], b[1]);
                        hmma(oc[2 * g + 1], pa[kt], b[2], b[3]);
                    }
                }
            }
            // overwrite Q slice h with O (own rows, own head cols only)
            #pragma unroll
            for (int j = 0; j < 4; j++) {
                int col = h * 32 + 8 * j + n_c;
                *(__half2*)(sm + QS_OFF + m_r * 400 + col * 2) =
                    __floats2half2_rn(oc[j][0], oc[j][1]);
                *(__half2*)(sm + QS_OFF + (m_r + 8) * 400 + col * 2) =
                    __floats2half2_rn(oc[j][2], oc[j][3]);
            }
        }
    }
    __syncthreads();     // all O written

    // ================= phase 3: proj GEMM, 6 chunks of 32 ==================
    #pragma unroll
    for (int k = 0; k < 12; k++) ldsm4(af[k], aRowQ + k * 32);   // O frags
    CPWAIT0();           // proj chunk 0 (prefetched before phase 2)
    __syncthreads();

    const size_t gbase = (size_t)blockIdx.x * 64;
    for (int g = 0; g < 6; g++) {
        if (g < 5) {
            prefetch32(smb + WBU_OFF + ((g + 1) & 1) * WB_SZ,
                       g_wp + (g + 1) * 32 * 192, tid);
            CPCOMMIT();
        }
        float acc[2][4] = {};
        uint32_t bRow = smb + WBU_OFF + (g & 1) * WB_SZ + bSel;
        #pragma unroll
        for (int k = 0; k < 12; k++) {
            uint32_t b[4]; ldsm4(b, bRow + k * 32);
            hmma(acc[0], af[k], b[0], b[1]);
            hmma(acc[1], af[k], b[2], b[3]);
        }
        #pragma unroll
        for (int jj = 0; jj < 2; jj++) {
            int col = g * 32 + ng * 16 + n_c + 8 * jj;
            float b0 = __ldg(proj_b + col), b1 = __ldg(proj_b + col + 1);
            *(float2*)(out + (gbase + m_r) * 192 + col) =
                make_float2(acc[jj][0] + b0, acc[jj][1] + b1);
            *(float2*)(out + (gbase + m_r + 8) * 192 + col) =
                make_float2(acc[jj][2] + b0, acc[jj][3] + b1);
        }
        if (g < 5) { CPWAIT0(); __syncthreads(); }
    }
}

// ---------------------------------------------------------------------------
extern "C" void kernel_launch(void* const* d_in, const int* in_sizes, int n_in,
                              void* d_out, int out_size)
{
    const float* x          = (const float*)d_in[0];
    const float* qkv_w      = (const float*)d_in[1];
    const float* qkv_b      = (const float*)d_in[2];
    const float* proj_w     = (const float*)d_in[3];
    const float* proj_b     = (const float*)d_in[4];
    const float* bias_table = (const float*)d_in[5];
    const int*   rel_idx    = (const int*)d_in[6];
    float* out = (float*)d_out;
    (void)n_in; (void)out_size;

    int B = in_sizes[0] / (64 * DIMC);    // 4096 windows

    cudaFuncSetAttribute(wa_main, cudaFuncAttributeMaxDynamicSharedMemorySize,
                         SM_TOTAL);

    wa_prep<<<432, 256>>>(qkv_w, proj_w);
    wa_main<<<B, 256, SM_TOTAL>>>(x, qkv_b, proj_b, bias_table, rel_idx, out);
}